// round 3
// baseline (speedup 1.0000x reference)
#include <cuda_runtime.h>
#include <math.h>

#define H 768
#define SEQ 512
#define VOC 30522
#define BATCH 8
#define TMAXX 32
#define EXT (VOC + SEQ)          /* 31034 */
#define X3H (3*H)                /* 2304 */
#define NEGV -1e6f
#define D1 (BATCH*TMAXX*EXT)     /* 7944704 */

// ---------------- persistent device scratch (no allocation) ----------------
__device__ __align__(16) float g_hA[BATCH*H];
__device__ __align__(16) float g_hB[BATCH*H];
__device__ __align__(16) float g_x[BATCH*X3H];      // [context | sel | embedded] per batch
__device__ float g_css[BATCH*SEQ];                   // copy_score_seq
__device__ float g_copyval[BATCH*VOC];               // accumulated copy score per present token
__device__ __align__(16) float g_gen[VOC*BATCH];     // gen logits, layout [v][b]
__device__ unsigned int       g_amax[BATCH];         // max key over gen+copy (for softmax max)
__device__ unsigned long long g_amax2[BATCH];        // argmax key over log_probs
__device__ float g_Zp[31][BATCH];                    // deterministic Z partials
__device__ unsigned char g_present[BATCH*VOC];
__device__ unsigned char g_fo[BATCH*SEQ];            // first-occurrence mask

__device__ __forceinline__ unsigned int okey(float f){
    unsigned int u = __float_as_uint(f);
    return (u & 0x80000000u) ? ~u : (u | 0x80000000u);
}
__device__ __forceinline__ float dekey(unsigned int u){
    return (u & 0x80000000u) ? __uint_as_float(u & 0x7FFFFFFFu)
                             : __uint_as_float(~u);
}
__device__ __forceinline__ const float* hsel(int p){ return p ? g_hB : g_hA; }
__device__ __forceinline__ float*       hselw(int p){ return p ? g_hB : g_hA; }

// ---------------- setup: sos row, tail col0, zero state, initial embedding ----------------
__global__ void k_init(const int* __restrict__ cls, const float* __restrict__ emb,
                       float* __restrict__ out, int has_tail){
    int i = blockIdx.x*blockDim.x + threadIdx.x;
    if (i < BATCH*EXT){
        int b = i/EXT, k = i - b*EXT;
        out[(size_t)b*TMAXX*EXT + k] = (k==0) ? (float)(*cls) : 0.f;
    }
    if (i < BATCH*VOC) g_present[i] = 0;
    if (i < BATCH*H){
        int b = i/H, j = i - b*H;
        g_hA[i] = 0.f;
        g_x[b*X3H + H   + j] = 0.f;          // sel = 0
        g_x[b*X3H + 2*H + j] = emb[H + j];   // embedded = emb[1]
    }
    if (has_tail && i < BATCH) out[D1 + i*TMAXX] = 1.0f;
}

// ---------------- precompute first-occurrence + present (inputs are static) ----------------
__global__ void k_prep(const int* __restrict__ inputs){
    int b = blockIdx.x, tid = threadIdx.x;    // 512 threads
    __shared__ int ins[SEQ];
    ins[tid] = inputs[b*SEQ + tid];
    __syncthreads();
    int t = ins[tid];
    int fo = (t != 0);                         // token 0 forced "missing"
    for (int s = 0; s < tid; s++) if (ins[s] == t) fo = 0;
    g_fo[b*SEQ + tid] = (unsigned char)fo;
    if (fo) g_present[b*VOC + t] = 1;
}

// ---------------- K1: attention + context; also resets step scratch ----------------
__global__ void k_attn(const float* __restrict__ enc, const float* __restrict__ aw,
                       const float* __restrict__ ab, int par){
    int b = blockIdx.x, tid = threadIdx.x;     // 768 threads, 24 warps
    const float* hin = hsel(par);
    __shared__ float hs[H], ths[H], sc[SEQ], red[256];
    if (tid == 0){ g_amax[b] = 0u; g_amax2[b] = 0ull; }
    if (tid < H) hs[tid] = hin[b*H + tid];
    __syncthreads();
    int warp = tid >> 5, lane = tid & 31;
    for (int j = warp; j < H; j += 24){
        float a = 0.f; const float* r = aw + (size_t)j*H;
        for (int i = lane; i < H; i += 32) a += hs[i]*r[i];
        #pragma unroll
        for (int o = 16; o; o >>= 1) a += __shfl_xor_sync(0xffffffffu, a, o);
        if (!lane) ths[j] = a + ab[j];
    }
    __syncthreads();
    for (int s = warp; s < SEQ; s += 24){
        float a = 0.f; const float* e = enc + ((size_t)b*SEQ + s)*H;
        for (int i = lane; i < H; i += 32) a += e[i]*ths[i];
        #pragma unroll
        for (int o = 16; o; o >>= 1) a += __shfl_xor_sync(0xffffffffu, a, o);
        if (!lane) sc[s] = a;
    }
    __syncthreads();
    // softmax over sc[0..511]
    if (tid < 256) red[tid] = fmaxf(sc[tid], sc[tid+256]);
    __syncthreads();
    for (int st = 128; st; st >>= 1){ if (tid < st) red[tid] = fmaxf(red[tid], red[tid+st]); __syncthreads(); }
    float m = red[0];
    __syncthreads();
    if (tid < SEQ) sc[tid] = expf(sc[tid] - m);
    __syncthreads();
    if (tid < 256) red[tid] = sc[tid] + sc[tid+256];
    __syncthreads();
    for (int st = 128; st; st >>= 1){ if (tid < st) red[tid] += red[tid+st]; __syncthreads(); }
    float inv = 1.f/red[0];
    __syncthreads();
    if (tid < SEQ) sc[tid] *= inv;
    __syncthreads();
    if (tid < H){
        float a = 0.f;
        for (int s = 0; s < SEQ; s++) a += sc[s]*enc[((size_t)b*SEQ + s)*H + tid];
        g_x[b*X3H + tid] = a;                      // context slot
    }
}

// ---------------- K2: GRU cell (warp per output index i, 8 batches per warp) ----------------
__global__ void k_gru(const float* __restrict__ wih, const float* __restrict__ whh,
                      const float* __restrict__ bih, const float* __restrict__ bhh, int par){
    int gw = blockIdx.x*(blockDim.x >> 5) + (threadIdx.x >> 5);
    int lane = threadIdx.x & 31;
    if (gw >= H) return;
    const float* hin  = hsel(par);
    float*       hout = hselw(par ^ 1);
    const float* wr = wih + (size_t)gw*X3H;
    const float* wz = wih + (size_t)(gw+H)*X3H;
    const float* wn = wih + (size_t)(gw+2*H)*X3H;
    const float* hr = whh + (size_t)gw*H;
    const float* hz = whh + (size_t)(gw+H)*H;
    const float* hn = whh + (size_t)(gw+2*H)*H;
    float air[8]={0,0,0,0,0,0,0,0}, aiz[8]={0,0,0,0,0,0,0,0}, ain[8]={0,0,0,0,0,0,0,0};
    float ahr[8]={0,0,0,0,0,0,0,0}, ahz[8]={0,0,0,0,0,0,0,0}, ahn[8]={0,0,0,0,0,0,0,0};
    for (int jb = 0; jb < X3H; jb += 32){
        int j = jb + lane;
        float fr = wr[j], fz = wz[j], fn = wn[j];
        #pragma unroll
        for (int b2 = 0; b2 < 8; b2++){
            float xv = g_x[b2*X3H + j];
            air[b2] += fr*xv; aiz[b2] += fz*xv; ain[b2] += fn*xv;
        }
    }
    for (int jb = 0; jb < H; jb += 32){
        int j = jb + lane;
        float fr = hr[j], fz = hz[j], fn = hn[j];
        #pragma unroll
        for (int b2 = 0; b2 < 8; b2++){
            float hv = hin[b2*H + j];
            ahr[b2] += fr*hv; ahz[b2] += fz*hv; ahn[b2] += fn*hv;
        }
    }
    #pragma unroll
    for (int o = 16; o; o >>= 1){
        #pragma unroll
        for (int b2 = 0; b2 < 8; b2++){
            air[b2] += __shfl_xor_sync(0xffffffffu, air[b2], o);
            aiz[b2] += __shfl_xor_sync(0xffffffffu, aiz[b2], o);
            ain[b2] += __shfl_xor_sync(0xffffffffu, ain[b2], o);
            ahr[b2] += __shfl_xor_sync(0xffffffffu, ahr[b2], o);
            ahz[b2] += __shfl_xor_sync(0xffffffffu, ahz[b2], o);
            ahn[b2] += __shfl_xor_sync(0xffffffffu, ahn[b2], o);
        }
    }
    if (lane == 0){
        float bir = bih[gw], biz = bih[gw+H], bin_ = bih[gw+2*H];
        float bhr = bhh[gw], bhz_ = bhh[gw+H], bhn = bhh[gw+2*H];
        #pragma unroll
        for (int b2 = 0; b2 < 8; b2++){
            float r = 1.f/(1.f + expf(-(air[b2] + bir + ahr[b2] + bhr)));
            float z = 1.f/(1.f + expf(-(aiz[b2] + biz + ahz[b2] + bhz_)));
            float n = tanhf((ain[b2] + bin_) + r*(ahn[b2] + bhn));
            float hp = hin[b2*H + gw];
            hout[b2*H + gw] = (1.f - z)*n + z*hp;
        }
    }
}

// ---------------- K3: copy scores (th2, css, deterministic token accumulation) ----------------
__global__ void k_copy(const float* __restrict__ enc, const float* __restrict__ cw,
                       const float* __restrict__ cb, const int* __restrict__ inputs, int par){
    int b = blockIdx.x, tid = threadIdx.x;     // 768 threads
    const float* hcur = hsel(par ^ 1);
    __shared__ float hs[H], ths[H], csss[SEQ];
    __shared__ int ins[SEQ];
    if (tid < H)  hs[tid] = hcur[b*H + tid];
    if (tid < SEQ) ins[tid] = inputs[b*SEQ + tid];
    __syncthreads();
    int warp = tid >> 5, lane = tid & 31;
    for (int j = warp; j < H; j += 24){
        float a = 0.f; const float* r = cw + (size_t)j*H;
        for (int i = lane; i < H; i += 32) a += hs[i]*r[i];
        #pragma unroll
        for (int o = 16; o; o >>= 1) a += __shfl_xor_sync(0xffffffffu, a, o);
        if (!lane) ths[j] = a + cb[j];
    }
    __syncthreads();
    for (int s = warp; s < SEQ; s += 24){
        float a = 0.f; const float* e = enc + ((size_t)b*SEQ + s)*H;
        for (int i = lane; i < H; i += 32) a += e[i]*ths[i];
        #pragma unroll
        for (int o = 16; o; o >>= 1) a += __shfl_xor_sync(0xffffffffu, a, o);
        if (!lane){ csss[s] = a; g_css[b*SEQ + s] = a; }
    }
    __syncthreads();
    if (tid < SEQ && g_fo[b*SEQ + tid]){
        int t = ins[tid]; float sum = 0.f;
        for (int s2 = 0; s2 < SEQ; s2++) if (ins[s2] == t) sum += csss[s2];
        g_copyval[b*VOC + t] = sum;
        atomicMax(&g_amax[b], okey(sum));      // copy contributes to softmax max
    }
}

// ---------------- K4: gen logits (warp per v, 8 batches) + per-batch max ----------------
__global__ void k_gen(const float4* __restrict__ ow4, const float* __restrict__ ob, int par){
    __shared__ float4 hs4[BATCH*(H/4)];        // 24 KB
    __shared__ unsigned int bmax[8];
    int tid = threadIdx.x;
    const float* hcur = hsel(par ^ 1);
    if (tid < 8) bmax[tid] = 0u;
    for (int i = tid; i < BATCH*H/4; i += blockDim.x) hs4[i] = ((const float4*)hcur)[i];
    __syncthreads();
    int warp = tid >> 5, lane = tid & 31;
    for (int v = blockIdx.x*8 + warp; v < VOC; v += gridDim.x*8){
        float acc[8] = {0,0,0,0,0,0,0,0};
        #pragma unroll
        for (int it = 0; it < 6; it++){
            float4 w = ow4[(size_t)v*192 + it*32 + lane];
            #pragma unroll
            for (int b2 = 0; b2 < 8; b2++){
                float4 hv = hs4[b2*192 + it*32 + lane];
                acc[b2] += w.x*hv.x + w.y*hv.y + w.z*hv.z + w.w*hv.w;
            }
        }
        #pragma unroll
        for (int o = 16; o; o >>= 1){
            #pragma unroll
            for (int b2 = 0; b2 < 8; b2++) acc[b2] += __shfl_xor_sync(0xffffffffu, acc[b2], o);
        }
        if (lane < 8){
            float g = acc[0];
            #pragma unroll
            for (int b2 = 1; b2 < 8; b2++) if (lane == b2) g = acc[b2];
            g += ob[v];
            if (v == 0) g = NEGV;
            g_gen[v*8 + lane] = g;
            atomicMax(&bmax[lane], okey(g));
        }
    }
    __syncthreads();
    if (tid < 8) atomicMax(&g_amax[tid], bmax[tid]);
}

// ---------------- K5: deterministic Z partials (gen chunks + copy terms) ----------------
__global__ void k_z(const int* __restrict__ inputs){
    int blk = blockIdx.x, tid = threadIdx.x;   // 31 blocks x 256
    int warp = tid >> 5, lane = tid & 31;
    float m[8];
    #pragma unroll
    for (int b2 = 0; b2 < 8; b2++) m[b2] = dekey(g_amax[b2]);
    if (blk < 30){
        int v0 = blk*1018, v1 = min(v0 + 1018, VOC);
        float acc[8] = {0,0,0,0,0,0,0,0};
        for (int v = v0 + tid; v < v1; v += 256){
            float4 a = *(const float4*)(g_gen + (size_t)v*8);
            float4 c = *(const float4*)(g_gen + (size_t)v*8 + 4);
            acc[0] += expf(a.x - m[0]); acc[1] += expf(a.y - m[1]);
            acc[2] += expf(a.z - m[2]); acc[3] += expf(a.w - m[3]);
            acc[4] += expf(c.x - m[4]); acc[5] += expf(c.y - m[5]);
            acc[6] += expf(c.z - m[6]); acc[7] += expf(c.w - m[7]);
        }
        #pragma unroll
        for (int o = 16; o; o >>= 1){
            #pragma unroll
            for (int b2 = 0; b2 < 8; b2++) acc[b2] += __shfl_xor_sync(0xffffffffu, acc[b2], o);
        }
        __shared__ float part[8][8];
        if (lane == 0){
            #pragma unroll
            for (int b2 = 0; b2 < 8; b2++) part[warp][b2] = acc[b2];
        }
        __syncthreads();
        if (tid < 8){
            float s = 0.f;
            for (int w = 0; w < 8; w++) s += part[w][tid];
            g_Zp[blk][tid] = s;
        }
    } else {
        int b2 = warp;                          // warp per batch
        float e = 0.f;
        for (int s = lane; s < SEQ; s += 32)
            if (g_fo[b2*SEQ + s])
                e += expf(g_copyval[b2*VOC + inputs[b2*SEQ + s]] - m[b2]);
        #pragma unroll
        for (int o = 16; o; o >>= 1) e += __shfl_xor_sync(0xffffffffu, e, o);
        if (!lane) g_Zp[30][b2] = e;
    }
}

// ---------------- K6: write log_probs row + argmax keys ----------------
__global__ void k_lp(float* __restrict__ out, int step){
    __shared__ float ms[8], zs[8];
    __shared__ unsigned long long bkey[8];
    int tid = threadIdx.x;
    if (tid < 8){
        ms[tid] = dekey(g_amax[tid]);
        float s = 0.f;
        for (int i = 0; i < 31; i++) s += g_Zp[i][tid];
        zs[tid] = 1.f/s;
        bkey[tid] = 0ull;
    }
    __syncthreads();
    int k = blockIdx.x*256 + tid;
    if (k < EXT){
        if (k >= VOC){
            float val = logf(1e-10f);
            #pragma unroll
            for (int b2 = 0; b2 < 8; b2++)
                out[((size_t)b2*TMAXX + step)*EXT + k] = val;
        } else {
            float4 a = *(const float4*)(g_gen + (size_t)k*8);
            float4 c = *(const float4*)(g_gen + (size_t)k*8 + 4);
            float gv[8] = {a.x,a.y,a.z,a.w,c.x,c.y,c.z,c.w};
            #pragma unroll
            for (int b2 = 0; b2 < 8; b2++){
                float p = expf(gv[b2] - ms[b2])*zs[b2];
                if (g_present[b2*VOC + k])
                    p += expf(g_copyval[b2*VOC + k] - ms[b2])*zs[b2];
                float lp = logf(p + 1e-10f);
                out[((size_t)b2*TMAXX + step)*EXT + k] = lp;
                unsigned long long key = (((unsigned long long)okey(lp)) << 32)
                                       | (unsigned int)(0x7FFFFFFF - k);
                atomicMax(&bkey[b2], key);
            }
        }
    }
    __syncthreads();
    if (tid < 8) atomicMax(&g_amax2[tid], bkey[tid]);
}

// ---------------- K7: sample, tail write, next embedding, selective read ----------------
__global__ void k_fin(const float* __restrict__ enc, const int* __restrict__ inputs,
                      const float* __restrict__ emb, float* __restrict__ out,
                      int step, int has_tail){
    int b = blockIdx.x, tid = threadIdx.x;     // 768 threads
    __shared__ float ws[SEQ], red[256];
    __shared__ int samp;
    if (tid == 0){
        unsigned long long key = g_amax2[b];
        samp = 0x7FFFFFFF - (int)(unsigned int)(key & 0xFFFFFFFFull);
        if (has_tail) out[D1 + b*TMAXX + step] = (float)samp;
    }
    __syncthreads();
    int k = samp;
    int kc = (k > VOC) ? 3 : min(k, VOC - 1);  // replicate JAX clamp semantics
    if (tid < H) g_x[b*X3H + 2*H + tid] = emb[(size_t)kc*H + tid];
    if (tid < SEQ) ws[tid] = (inputs[b*SEQ + tid] == k) ? g_css[b*SEQ + tid] : 0.f;
    __syncthreads();
    if (tid < 256) red[tid] = fabsf(ws[tid]) + fabsf(ws[tid+256]);
    __syncthreads();
    for (int st = 128; st; st >>= 1){ if (tid < st) red[tid] += red[tid+st]; __syncthreads(); }
    float denom = fmaxf(red[0], 1e-12f);
    __syncthreads();
    if (tid < SEQ) ws[tid] /= denom;
    __syncthreads();
    if (tid < H){
        float a = 0.f;
        for (int s = 0; s < SEQ; s++) a += ws[s]*enc[((size_t)b*SEQ + s)*H + tid];
        g_x[b*X3H + H + tid] = a;              // sel slot for next step
    }
}

// ---------------- host ----------------
extern "C" void kernel_launch(void* const* d_in, const int* in_sizes, int n_in,
                              void* d_out, int out_size){
    const float* enc    = (const float*)d_in[0];
    const int*   inputs = (const int*)  d_in[1];
    const int*   cls    = (const int*)  d_in[2];
    /* d_in[3] sep_to unused */
    const float* emb    = (const float*)d_in[4];
    const float* aw     = (const float*)d_in[5];
    const float* ab     = (const float*)d_in[6];
    const float* cw     = (const float*)d_in[7];
    const float* cb     = (const float*)d_in[8];
    const float* wih    = (const float*)d_in[9];
    const float* whh    = (const float*)d_in[10];
    const float* bih    = (const float*)d_in[11];
    const float* bhh    = (const float*)d_in[12];
    const float* ow     = (const float*)d_in[13];
    const float* ob     = (const float*)d_in[14];
    float* out = (float*)d_out;
    int has_tail = (out_size >= D1 + BATCH*TMAXX) ? 1 : 0;

    k_init<<<(BATCH*EXT + 255)/256, 256>>>(cls, emb, out, has_tail);
    k_prep<<<BATCH, SEQ>>>(inputs);

    for (int step = 1; step < TMAXX; step++){
        int par = (step - 1) & 1;                       // h_in = buf[par], h_out = buf[par^1]
        k_attn<<<BATCH, 768>>>(enc, aw, ab, par);
        k_gru <<<192, 128>>>(wih, whh, bih, bhh, par);
        k_copy<<<BATCH, 768>>>(enc, cw, cb, inputs, par);
        k_gen <<<592, 256>>>((const float4*)ow, ob, par);
        k_z   <<<31, 256>>>(inputs);
        k_lp  <<<(EXT + 255)/256, 256>>>(out, step);
        k_fin <<<BATCH, 768>>>(enc, inputs, emb, out, step, has_tail);
    }
}

// round 4
// speedup vs baseline: 1.4162x; 1.4162x over previous
#include <cuda_runtime.h>
#include <math.h>

#define H 768
#define H4 192
#define SEQ 512
#define VOC 30522
#define BATCH 8
#define TMAXX 32
#define EXT (VOC+SEQ)
#define X3H (3*H)
#define X3H4 (X3H/4)
#define NEGV -1e6f
#define D1 (BATCH*TMAXX*EXT)
#define NCTA 148
#define NW (NCTA*32)

// ---------------- persistent device scratch ----------------
__device__ __align__(16) float g_h[2][BATCH*H];
__device__ __align__(16) float g_x[BATCH*X3H];
__device__ __align__(16) float g_th[BATCH*H];
__device__ float g_sc[BATCH*SEQ];
__device__ float g_ws[BATCH*SEQ];
__device__ float g_invden[BATCH];
__device__ float g_css[BATCH*SEQ];
__device__ __align__(16) float g_gRZ[2][BATCH][H];
__device__ __align__(16) float g_gNi[BATCH][H];
__device__ __align__(16) float g_gNh[BATCH][H];
__device__ float g_copyval[BATCH*VOC];
__device__ __align__(16) float g_gen[VOC*8];
__device__ unsigned int       g_amax[BATCH];
__device__ unsigned long long g_amax2[BATCH];
__device__ float g_Zp[NCTA+1][BATCH];
__device__ unsigned char g_present[BATCH*VOC];
__device__ unsigned char g_fo[BATCH*SEQ];
__device__ unsigned int g_bar;

__device__ __forceinline__ unsigned int okey(float f){
    unsigned int u = __float_as_uint(f);
    return (u & 0x80000000u) ? ~u : (u | 0x80000000u);
}
__device__ __forceinline__ float dekey(unsigned int u){
    return (u & 0x80000000u) ? __uint_as_float(u & 0x7FFFFFFFu)
                             : __uint_as_float(~u);
}
__device__ __forceinline__ float wred(float a){
    #pragma unroll
    for (int o = 16; o; o >>= 1) a += __shfl_xor_sync(0xffffffffu, a, o);
    return a;
}
__device__ __forceinline__ float dot768(const float4* __restrict__ A,
                                        const float4* __restrict__ B, int lane){
    float a = 0.f;
    #pragma unroll
    for (int i = 0; i < 6; i++){
        float4 x = A[lane + 32*i], y = B[lane + 32*i];
        a += x.x*y.x + x.y*y.y + x.z*y.z + x.w*y.w;
    }
    return wred(a);
}
__device__ __forceinline__ float gruc(float rr, float zz, float ni, float nh, float ho){
    float r = 1.f/(1.f + expf(-rr));
    float z = 1.f/(1.f + expf(-zz));
    float n = tanhf(ni + r*nh);
    return (1.f - z)*n + z*ho;
}
// grid barrier: fence (gpu scope -> CCTL.IVALL L1 flush), count, spin
__device__ __forceinline__ void gridbar(unsigned int &target){
    __threadfence();
    __syncthreads();
    target += NCTA;
    if (threadIdx.x == 0){
        atomicAdd(&g_bar, 1u);
        while (*(volatile unsigned int*)&g_bar < target) { }
        __threadfence();
    }
    __syncthreads();
}

// ---------------- init ----------------
__global__ void k_init(const int* __restrict__ cls, const float* __restrict__ emb,
                       float* __restrict__ out, int has_tail){
    int i = blockIdx.x*blockDim.x + threadIdx.x;
    int n = gridDim.x*blockDim.x;
    if (i == 0) g_bar = 0u;
    for (int k = i; k < BATCH*EXT; k += n){
        int b = k/EXT, j = k - b*EXT;
        out[(size_t)b*TMAXX*EXT + j] = (j == 0) ? (float)(*cls) : 0.f;
    }
    const float L = logf(1e-10f);
    for (int k = i; k < BATCH*(TMAXX-1)*SEQ; k += n){
        int b = k/((TMAXX-1)*SEQ);
        int r = k - b*(TMAXX-1)*SEQ;
        int step = r/SEQ + 1;
        int s = r - (step-1)*SEQ;
        out[((size_t)b*TMAXX + step)*EXT + VOC + s] = L;
    }
    for (int k = i; k < BATCH*VOC; k += n) g_present[k] = 0;
    for (int k = i; k < BATCH*H; k += n){
        int b = k/H, j = k - b*H;
        g_h[0][k] = 0.f;
        g_x[b*X3H + H   + j] = 0.f;
        g_x[b*X3H + 2*H + j] = emb[H + j];
    }
    if (has_tail && i < BATCH) out[D1 + i*TMAXX] = 1.0f;
}

__global__ void k_prep(const int* __restrict__ inputs){
    int b = blockIdx.x, tid = threadIdx.x;
    __shared__ int ins[SEQ];
    ins[tid] = inputs[b*SEQ + tid];
    __syncthreads();
    int t = ins[tid];
    int fo = (t != 0);
    for (int s = 0; s < tid; s++) if (ins[s] == t) fo = 0;
    g_fo[b*SEQ + tid] = (unsigned char)fo;
    if (fo) g_present[b*VOC + t] = 1;
}

// ---------------- the persistent decode loop ----------------
__global__ void __launch_bounds__(1024, 1)
k_loop(const float* __restrict__ enc, const int* __restrict__ inputs,
       const float* __restrict__ emb,
       const float4* __restrict__ aw4, const float* __restrict__ ab,
       const float4* __restrict__ cw4, const float* __restrict__ cb,
       const float4* __restrict__ wih4, const float4* __restrict__ whh4,
       const float* __restrict__ bih, const float* __restrict__ bhh,
       const float4* __restrict__ ow4, const float* __restrict__ ob,
       float* __restrict__ out, int has_tail)
{
    const int tid = threadIdx.x, cta = blockIdx.x;
    const int wid = tid >> 5, lane = tid & 31;
    const int W = cta*32 + wid;
    unsigned int bt = 0;

    __shared__ float4 hs4[BATCH*H4];      // 24.5 KB
    __shared__ float th2s[H];
    __shared__ float csss[SEQ];
    __shared__ int   inss[SEQ];
    __shared__ float zred[32][8];
    __shared__ float zinv[8], msh[8];
    __shared__ unsigned long long bkey[8];
    __shared__ unsigned int bmax[8];

    for (int t = 1; t < TMAXX; t++){
        const float* hin = g_h[(t + 1) & 1];

        // ---- P1: th = attn_w @ h + b  (6144 warp tasks)  ||  finalize(t-1) (8 tasks)
        for (int task = W; task < 6144 + 8; task += NW){
            if (task < 6144){
                int b = task/H, j = task - b*H;
                float a = dot768(aw4 + (size_t)j*H4, (const float4*)(hin + b*H), lane);
                if (!lane) g_th[b*H + j] = a + ab[j];
            } else if (t > 1){
                int b = task - 6144;
                unsigned long long key = g_amax2[b];
                int samp = 0x7FFFFFFF - (int)(unsigned int)(key & 0xFFFFFFFFull);
                if (!lane && has_tail) out[D1 + b*TMAXX + (t-1)] = (float)samp;
                int kc = (samp > VOC) ? 3 : min(samp, VOC - 1);
                const float4* er = (const float4*)(emb + (size_t)kc*H);
                float4* xd = (float4*)(g_x + b*X3H + 2*H);
                #pragma unroll
                for (int i = 0; i < 6; i++) xd[lane + 32*i] = er[lane + 32*i];
                float ad = 0.f;
                #pragma unroll
                for (int i = 0; i < 16; i++){
                    int s = lane + 32*i;
                    float w = (inputs[b*SEQ + s] == samp) ? g_css[b*SEQ + s] : 0.f;
                    g_ws[b*SEQ + s] = w;
                    ad += fabsf(w);
                }
                ad = wred(ad);
                if (!lane) g_invden[b] = 1.f/fmaxf(ad, 1e-12f);
            }
        }
        gridbar(bt);

        // ---- P2: attention scores (4096 tasks) || selective-read(t-1) (192 tasks)
        for (int task = W; task < 4096 + 192; task += NW){
            if (task < 4096){
                int b = task >> 9, s = task & 511;
                float a = dot768((const float4*)(enc + ((size_t)b*SEQ + s)*H),
                                 (const float4*)(g_th + b*H), lane);
                if (!lane) g_sc[b*SEQ + s] = a;
            } else if (t > 1){
                int id = task - 4096;
                int b = id/24, c = id - b*24;
                int h0 = c*32 + lane;
                float inv = g_invden[b];
                float acc = 0.f;
                const float* ep = enc + (size_t)b*SEQ*H + h0;
                const float* wp = g_ws + b*SEQ;
                #pragma unroll 8
                for (int s = 0; s < SEQ; s++) acc += wp[s]*ep[(size_t)s*H];
                g_x[b*X3H + H + h0] = acc*inv;
            }
        }
        gridbar(bt);

        // ---- P3: softmax + context (192 tasks, coalesced h columns) + resets
        for (int task = W; task < 193; task += NW){
            if (task < 192){
                int b = task/24, c = task - b*24;
                int h0 = c*32 + lane;
                const float* sp = g_sc + b*SEQ;
                float mx = -1e30f;
                #pragma unroll
                for (int i = 0; i < 16; i++) mx = fmaxf(mx, sp[lane + 32*i]);
                #pragma unroll
                for (int o = 16; o; o >>= 1) mx = fmaxf(mx, __shfl_xor_sync(0xffffffffu, mx, o));
                float se = 0.f;
                #pragma unroll
                for (int i = 0; i < 16; i++) se += expf(sp[lane + 32*i] - mx);
                se = wred(se);
                float inv = 1.f/se;
                float acc = 0.f;
                const float* ep = enc + (size_t)b*SEQ*H + h0;
                for (int s0 = 0; s0 < SEQ; s0 += 32){
                    float w = expf(sp[s0 + lane] - mx)*inv;
                    #pragma unroll
                    for (int i = 0; i < 32; i++){
                        float wi = __shfl_sync(0xffffffffu, w, i);
                        acc += wi*ep[(size_t)(s0 + i)*H];
                    }
                }
                g_x[b*X3H + h0] = acc;
            } else {
                if (lane < 8){ g_amax[lane] = 0u; g_amax2[lane] = 0ull; }
            }
        }
        gridbar(bt);

        // ---- P4: GRU gate partials (4608 warp tasks: gate-row r, batch-half bh)
        for (int task = W; task < 4608; task += NW){
            int bh = task & 1;
            int r  = task >> 1;            // 0..2303 == g*768 + j
            int b0 = bh*4;
            const float4* wi = wih4 + (size_t)r*X3H4;
            const float4* wh = whh4 + (size_t)r*H4;
            float gi[4] = {0,0,0,0}, gh[4] = {0,0,0,0};
            for (int i = 0; i < 18; i++){
                float4 w = wi[lane + 32*i];
                #pragma unroll
                for (int q = 0; q < 4; q++){
                    float4 x = ((const float4*)(g_x + (size_t)(b0 + q)*X3H))[lane + 32*i];
                    gi[q] += w.x*x.x + w.y*x.y + w.z*x.z + w.w*x.w;
                }
            }
            #pragma unroll
            for (int i = 0; i < 6; i++){
                float4 w = wh[lane + 32*i];
                #pragma unroll
                for (int q = 0; q < 4; q++){
                    float4 x = ((const float4*)(hin + (size_t)(b0 + q)*H))[lane + 32*i];
                    gh[q] += w.x*x.x + w.y*x.y + w.z*x.z + w.w*x.w;
                }
            }
            #pragma unroll
            for (int q = 0; q < 4; q++){ gi[q] = wred(gi[q]); gh[q] = wred(gh[q]); }
            if (!lane){
                int g = r/H, j = r - g*H;
                float bi = bih[r], bh_ = bhh[r];
                if (g < 2){
                    #pragma unroll
                    for (int q = 0; q < 4; q++) g_gRZ[g][b0 + q][j] = gi[q] + gh[q] + bi + bh_;
                } else {
                    #pragma unroll
                    for (int q = 0; q < 4; q++){
                        g_gNi[b0 + q][j] = gi[q] + bi;
                        g_gNh[b0 + q][j] = gh[q] + bh_;
                    }
                }
            }
        }
        gridbar(bt);

        // ---- P5: local h combine; then gen logits (CTAs 8..147) || copy chain (CTAs 0..7)
        {
            float* hnew = g_h[t & 1];
            for (int m = tid; m < BATCH*H4; m += 1024){
                int b = m/H4, c = m - b*H4;
                float4 r0 = ((const float4*)g_gRZ[0][b])[c];
                float4 r1 = ((const float4*)g_gRZ[1][b])[c];
                float4 ni = ((const float4*)g_gNi[b])[c];
                float4 nh = ((const float4*)g_gNh[b])[c];
                float4 ho = ((const float4*)(hin + (size_t)b*H))[c];
                float4 hv;
                hv.x = gruc(r0.x, r1.x, ni.x, nh.x, ho.x);
                hv.y = gruc(r0.y, r1.y, ni.y, nh.y, ho.y);
                hv.z = gruc(r0.z, r1.z, ni.z, nh.z, ho.z);
                hv.w = gruc(r0.w, r1.w, ni.w, nh.w, ho.w);
                hs4[m] = hv;
                if (cta == 0) ((float4*)hnew)[m] = hv;
            }
            __syncthreads();

            if (cta < 8){
                int b = cta;
                for (int j = wid*24; j < wid*24 + 24; j++){
                    float a = 0.f;
                    const float4* r4 = cw4 + (size_t)j*H4;
                    #pragma unroll
                    for (int i = 0; i < 6; i++){
                        float4 w = r4[lane + 32*i];
                        float4 h = hs4[b*H4 + lane + 32*i];
                        a += w.x*h.x + w.y*h.y + w.z*h.z + w.w*h.w;
                    }
                    a = wred(a);
                    if (!lane) th2s[j] = a + cb[j];
                }
                if (tid < SEQ) inss[tid] = inputs[b*SEQ + tid];
                __syncthreads();
                for (int s = wid*16; s < wid*16 + 16; s++){
                    float a = 0.f;
                    const float4* e4 = (const float4*)(enc + ((size_t)b*SEQ + s)*H);
                    const float4* t4 = (const float4*)th2s;
                    #pragma unroll
                    for (int i = 0; i < 6; i++){
                        float4 w = e4[lane + 32*i];
                        float4 h = t4[lane + 32*i];
                        a += w.x*h.x + w.y*h.y + w.z*h.z + w.w*h.w;
                    }
                    a = wred(a);
                    if (!lane){ csss[s] = a; g_css[b*SEQ + s] = a; }
                }
                __syncthreads();
                if (tid < SEQ && g_fo[b*SEQ + tid]){
                    int tok = inss[tid];
                    float sum = 0.f;
                    for (int s = 0; s < SEQ; s++) if (inss[s] == tok) sum += csss[s];
                    g_copyval[b*VOC + tok] = sum;
                    atomicMax(&g_amax[b], okey(sum));
                }
            } else {
                if (tid < 8) bmax[tid] = 0u;
                __syncthreads();
                for (int v = (cta - 8)*32 + wid; v < VOC; v += 4480){
                    float acc[8] = {0,0,0,0,0,0,0,0};
                    #pragma unroll
                    for (int i = 0; i < 6; i++){
                        float4 w = ow4[(size_t)v*H4 + i*32 + lane];
                        #pragma unroll
                        for (int b2 = 0; b2 < 8; b2++){
                            float4 h = hs4[b2*H4 + i*32 + lane];
                            acc[b2] += w.x*h.x + w.y*h.y + w.z*h.z + w.w*h.w;
                        }
                    }
                    #pragma unroll
                    for (int o = 16; o; o >>= 1){
                        #pragma unroll
                        for (int b2 = 0; b2 < 8; b2++)
                            acc[b2] += __shfl_xor_sync(0xffffffffu, acc[b2], o);
                    }
                    if (lane < 8){
                        float gv = acc[0];
                        #pragma unroll
                        for (int b2 = 1; b2 < 8; b2++) if (lane == b2) gv = acc[b2];
                        gv += ob[v];
                        if (v == 0) gv = NEGV;
                        g_gen[(size_t)v*8 + lane] = gv;
                        atomicMax(&bmax[lane], okey(gv));
                    }
                }
                __syncthreads();
                if (tid < 8) atomicMax(&g_amax[tid], bmax[tid]);
            }
        }
        gridbar(bt);

        // ---- P6: deterministic Z partials (per-CTA vocab chunk) + copy-Z
        {
            float m8[8];
            #pragma unroll
            for (int b = 0; b < 8; b++) m8[b] = dekey(g_amax[b]);
            int v0 = cta*207;
            int cnt = min(207, VOC - v0);
            float e[8] = {0,0,0,0,0,0,0,0};
            if (tid < cnt){
                int v = v0 + tid;
                float4 a = ((const float4*)g_gen)[(size_t)v*2];
                float4 c = ((const float4*)g_gen)[(size_t)v*2 + 1];
                e[0] = expf(a.x - m8[0]); e[1] = expf(a.y - m8[1]);
                e[2] = expf(a.z - m8[2]); e[3] = expf(a.w - m8[3]);
                e[4] = expf(c.x - m8[4]); e[5] = expf(c.y - m8[5]);
                e[6] = expf(c.z - m8[6]); e[7] = expf(c.w - m8[7]);
            }
            #pragma unroll
            for (int o = 16; o; o >>= 1){
                #pragma unroll
                for (int b = 0; b < 8; b++) e[b] += __shfl_xor_sync(0xffffffffu, e[b], o);
            }
            if (!lane){
                #pragma unroll
                for (int b = 0; b < 8; b++) zred[wid][b] = e[b];
            }
            __syncthreads();
            if (wid < 8){
                float v = zred[lane][wid];
                v = wred(v);
                if (!lane) g_Zp[cta][wid] = v;
            }
            if (cta == NCTA - 1 && wid >= 16 && wid < 24){
                int b = wid - 16;
                float e2 = 0.f;
                for (int s = lane; s < SEQ; s += 32)
                    if (g_fo[b*SEQ + s])
                        e2 += expf(g_copyval[b*VOC + inputs[b*SEQ + s]] - m8[b]);
                e2 = wred(e2);
                if (!lane) g_Zp[NCTA][b] = e2;
            }
        }
        gridbar(bt);

        // ---- P7: log-prob row write + argmax keys (per-CTA vocab chunk)
        {
            if (tid < 8){
                float z = 0.f;
                for (int i = 0; i <= NCTA; i++) z += g_Zp[i][tid];
                zinv[tid] = 1.f/z;
                msh[tid] = dekey(g_amax[tid]);
                bkey[tid] = 0ull;
            }
            __syncthreads();
            int v0 = cta*207;
            int cnt = min(207, VOC - v0);
            if (tid < cnt){
                int v = v0 + tid;
                float4 a = ((const float4*)g_gen)[(size_t)v*2];
                float4 c = ((const float4*)g_gen)[(size_t)v*2 + 1];
                float gv[8] = {a.x, a.y, a.z, a.w, c.x, c.y, c.z, c.w};
                unsigned int vk = (unsigned int)(0x7FFFFFFF - v);
                #pragma unroll
                for (int b = 0; b < 8; b++){
                    float p = expf(gv[b] - msh[b])*zinv[b];
                    if (g_present[b*VOC + v])
                        p += expf(g_copyval[b*VOC + v] - msh[b])*zinv[b];
                    float lp = logf(p + 1e-10f);
                    out[((size_t)b*TMAXX + t)*EXT + v] = lp;
                    unsigned long long key = (((unsigned long long)okey(lp)) << 32) | vk;
                    atomicMax(&bkey[b], key);
                }
            }
            __syncthreads();
            if (tid < 8) atomicMax(&g_amax2[tid], bkey[tid]);
        }
        gridbar(bt);
    }

    // final sampled index for step 31
    if (cta == 0 && tid < 8 && has_tail){
        unsigned long long key = g_amax2[tid];
        int samp = 0x7FFFFFFF - (int)(unsigned int)(key & 0xFFFFFFFFull);
        out[D1 + tid*TMAXX + (TMAXX - 1)] = (float)samp;
    }
}

// ---------------- host ----------------
extern "C" void kernel_launch(void* const* d_in, const int* in_sizes, int n_in,
                              void* d_out, int out_size){
    const float* enc    = (const float*)d_in[0];
    const int*   inputs = (const int*)  d_in[1];
    const int*   cls    = (const int*)  d_in[2];
    /* d_in[3] sep_to unused */
    const float* emb    = (const float*)d_in[4];
    const float* aw     = (const float*)d_in[5];
    const float* ab     = (const float*)d_in[6];
    const float* cw     = (const float*)d_in[7];
    const float* cb     = (const float*)d_in[8];
    const float* wih    = (const float*)d_in[9];
    const float* whh    = (const float*)d_in[10];
    const float* bih    = (const float*)d_in[11];
    const float* bhh    = (const float*)d_in[12];
    const float* ow     = (const float*)d_in[13];
    const float* ob     = (const float*)d_in[14];
    float* out = (float*)d_out;
    int has_tail = (out_size >= D1 + BATCH*TMAXX) ? 1 : 0;

    k_init<<<512, 256>>>(cls, emb, out, has_tail);
    k_prep<<<BATCH, SEQ>>>(inputs);
    k_loop<<<NCTA, 1024>>>(enc, inputs, emb,
                           (const float4*)aw, ab,
                           (const float4*)cw, cb,
                           (const float4*)wih, (const float4*)whh,
                           bih, bhh,
                           (const float4*)ow, ob,
                           out, has_tail);
}

// round 5
// speedup vs baseline: 2.7353x; 1.9314x over previous
#include <cuda_runtime.h>
#include <math.h>

#define H 768
#define H4 192
#define SEQ 512
#define VOC 30522
#define BATCH 8
#define TMAXX 32
#define EXT (VOC+SEQ)
#define X3H (3*H)
#define X3H4 (X3H/4)
#define NEGV -1e6f
#define D1 (BATCH*TMAXX*EXT)
#define NCTA 148
#define NTHR 512
#define NWARP 16
#define NW (NCTA*NWARP)          /* 2368 warps */
#define GBLK ((VOC+3)/4)         /* 7631 gen blocks of 4 vocab rows */
#define GEN_E 2700
#define GEN_F 5100
#define ZCH 207                  /* vocab chunk per CTA for Z/lp */

// ---------------- persistent device scratch ----------------
__device__ __align__(16) float g_x[BATCH*X3H];     // [ctx | sel | emb]
__device__ __align__(16) float g_th[BATCH*H];
__device__ __align__(16) float g_th2[BATCH*H];
__device__ float g_sc[BATCH*SEQ];
__device__ float g_ws[BATCH*SEQ];
__device__ float g_invden[BATCH];
__device__ float g_css[BATCH*SEQ];
__device__ __align__(16) float g_gRZ[2][BATCH][H];
__device__ __align__(16) float g_gNi[BATCH][H];
__device__ __align__(16) float g_gNh[BATCH][H];
__device__ float g_copyval[BATCH*VOC];
__device__ __align__(16) float g_gen[VOC*8];
__device__ unsigned int       g_amax[BATCH];
__device__ unsigned long long g_amax2[BATCH];
__device__ float g_Zp[NCTA+1][BATCH];
__device__ unsigned char g_present[BATCH*VOC];
__device__ unsigned char g_fo[BATCH*SEQ];
__device__ unsigned int g_bar;

__device__ __forceinline__ unsigned int okey(float f){
    unsigned int u = __float_as_uint(f);
    return (u & 0x80000000u) ? ~u : (u | 0x80000000u);
}
__device__ __forceinline__ float dekey(unsigned int u){
    return (u & 0x80000000u) ? __uint_as_float(u & 0x7FFFFFFFu)
                             : __uint_as_float(~u);
}
__device__ __forceinline__ float wred(float a){
    #pragma unroll
    for (int o = 16; o; o >>= 1) a += __shfl_xor_sync(0xffffffffu, a, o);
    return a;
}
__device__ __forceinline__ float gruc(float rr, float zz, float ni, float nh, float ho){
    float r = 1.f/(1.f + expf(-rr));
    float z = 1.f/(1.f + expf(-zz));
    float n = tanhf(ni + r*nh);
    return (1.f - z)*n + z*ho;
}
__device__ __forceinline__ void gridbar(unsigned int &target){
    __threadfence();
    __syncthreads();
    target += NCTA;
    if (threadIdx.x == 0){
        atomicAdd(&g_bar, 1u);
        while (*(volatile unsigned int*)&g_bar < target) { }
        __threadfence();
    }
    __syncthreads();
}

// ---------------- init ----------------
__global__ void k_init(const int* __restrict__ cls, const float* __restrict__ emb,
                       float* __restrict__ out, int has_tail){
    int i = blockIdx.x*blockDim.x + threadIdx.x;
    int n = gridDim.x*blockDim.x;
    if (i == 0) g_bar = 0u;
    for (int k = i; k < BATCH*EXT; k += n){
        int b = k/EXT, j = k - b*EXT;
        out[(size_t)b*TMAXX*EXT + j] = (j == 0) ? (float)(*cls) : 0.f;
    }
    const float L = logf(1e-10f);
    for (int k = i; k < BATCH*(TMAXX-1)*SEQ; k += n){
        int b = k/((TMAXX-1)*SEQ);
        int r = k - b*(TMAXX-1)*SEQ;
        int step = r/SEQ + 1;
        int s = r - (step-1)*SEQ;
        out[((size_t)b*TMAXX + step)*EXT + VOC + s] = L;
    }
    for (int k = i; k < BATCH*VOC; k += n) g_present[k] = 0;
    for (int k = i; k < BATCH*H; k += n){
        int b = k/H, j = k - b*H;
        g_x[b*X3H + H   + j] = 0.f;
        g_x[b*X3H + 2*H + j] = emb[H + j];
    }
    if (has_tail && i < BATCH) out[D1 + i*TMAXX] = 1.0f;
}

__global__ void k_prep(const int* __restrict__ inputs){
    int b = blockIdx.x, tid = threadIdx.x;
    __shared__ int ins[SEQ];
    ins[tid] = inputs[b*SEQ + tid];
    __syncthreads();
    int t = ins[tid];
    int fo = (t != 0);
    for (int s = 0; s < tid; s++) if (ins[s] == t) fo = 0;
    g_fo[b*SEQ + tid] = (unsigned char)fo;
    if (fo) g_present[b*VOC + t] = 1;
}

// ---------------- persistent decode loop ----------------
__global__ void __launch_bounds__(NTHR, 1)
k_loop(const float* __restrict__ enc, const int* __restrict__ inputs,
       const float* __restrict__ emb,
       const float4* __restrict__ aw4, const float* __restrict__ ab,
       const float4* __restrict__ cw4, const float* __restrict__ cb,
       const float4* __restrict__ wih4, const float4* __restrict__ whh4,
       const float* __restrict__ bih, const float* __restrict__ bhh,
       const float4* __restrict__ ow4, const float* __restrict__ ob,
       float* __restrict__ out, int has_tail)
{
    const int tid = threadIdx.x, cta = blockIdx.x;
    const int wid = tid >> 5, lane = tid & 31;
    const int W = cta*NWARP + wid;
    unsigned int bt = 0;

    extern __shared__ float smem[];
    float4* xs4 = (float4*)smem;                 // 8*576 float4 = 72 KB
    float4* hs4 = (float4*)(smem + BATCH*X3H);   // 8*192 float4 = 24 KB

    __shared__ float zred[NWARP][8];
    __shared__ float zinv[8], msh[8];
    __shared__ unsigned long long bkey[8];
    __shared__ unsigned int bmax[8];

    // h0 = 0 (CTA-local copy of hidden state)
    for (int m = tid; m < BATCH*H4; m += NTHR) hs4[m] = make_float4(0.f,0.f,0.f,0.f);
    __syncthreads();

    for (int t = 1; t < TMAXX; t++){
        // ===== A: th = attn_w@h + b  (1536 tasks)  || finalize(t-1) (8)
        for (int task = W; task < 1536 + 8; task += NW){
            if (task < 1536){
                int bh = task & 1, j = task >> 1;
                int b0 = bh*4;
                const float4* r4 = aw4 + (size_t)j*H4;
                float a0=0,a1=0,a2=0,a3=0;
                #pragma unroll
                for (int i = 0; i < 6; i++){
                    float4 w = r4[i*32 + lane];
                    float4 h0 = hs4[(b0+0)*H4 + i*32 + lane];
                    float4 h1 = hs4[(b0+1)*H4 + i*32 + lane];
                    float4 h2 = hs4[(b0+2)*H4 + i*32 + lane];
                    float4 h3 = hs4[(b0+3)*H4 + i*32 + lane];
                    a0 += w.x*h0.x + w.y*h0.y + w.z*h0.z + w.w*h0.w;
                    a1 += w.x*h1.x + w.y*h1.y + w.z*h1.z + w.w*h1.w;
                    a2 += w.x*h2.x + w.y*h2.y + w.z*h2.z + w.w*h2.w;
                    a3 += w.x*h3.x + w.y*h3.y + w.z*h3.z + w.w*h3.w;
                }
                a0 = wred(a0); a1 = wred(a1); a2 = wred(a2); a3 = wred(a3);
                if (!lane){
                    float bb = ab[j];
                    g_th[(b0+0)*H + j] = a0 + bb;
                    g_th[(b0+1)*H + j] = a1 + bb;
                    g_th[(b0+2)*H + j] = a2 + bb;
                    g_th[(b0+3)*H + j] = a3 + bb;
                }
            } else if (t > 1){
                int b = task - 1536;
                unsigned long long key = g_amax2[b];
                int samp = 0x7FFFFFFF - (int)(unsigned int)(key & 0xFFFFFFFFull);
                if (!lane && has_tail) out[D1 + b*TMAXX + (t-1)] = (float)samp;
                int kc = (samp > VOC) ? 3 : min(samp, VOC - 1);
                const float4* er = (const float4*)(emb + (size_t)kc*H);
                float4* xd = (float4*)(g_x + b*X3H + 2*H);
                #pragma unroll
                for (int i = 0; i < 6; i++) xd[lane + 32*i] = er[lane + 32*i];
                float ad = 0.f;
                #pragma unroll
                for (int i = 0; i < 16; i++){
                    int s = lane + 32*i;
                    float w = (inputs[b*SEQ + s] == samp) ? g_css[b*SEQ + s] : 0.f;
                    g_ws[b*SEQ + s] = w;
                    ad += fabsf(w);
                }
                ad = wred(ad);
                if (!lane) g_invden[b] = 1.f/fmaxf(ad, 1e-12f);
            }
        }
        gridbar(bt);

        // ===== B: attention scores (4096) || selective-read(t-1) (192)
        for (int task = W; task < 4096 + 192; task += NW){
            if (task < 4096){
                int b = task >> 9, s = task & 511;
                const float4* e4 = (const float4*)(enc + ((size_t)b*SEQ + s)*H);
                const float4* t4 = (const float4*)(g_th + b*H);
                float a = 0.f;
                #pragma unroll
                for (int i = 0; i < 6; i++){
                    float4 x = e4[i*32 + lane], y = t4[i*32 + lane];
                    a += x.x*y.x + x.y*y.y + x.z*y.z + x.w*y.w;
                }
                a = wred(a);
                if (!lane) g_sc[b*SEQ + s] = a;
            } else if (t > 1){
                int id = task - 4096;
                int b = id/24, c = id - b*24;
                int h0 = c*32 + lane;
                float inv = g_invden[b];
                const float* ep = enc + (size_t)b*SEQ*H + h0;
                const float* wp = g_ws + b*SEQ;
                float a0=0,a1=0,a2=0,a3=0;
                for (int s = 0; s < SEQ; s += 4){
                    a0 += wp[s+0]*ep[(size_t)(s+0)*H];
                    a1 += wp[s+1]*ep[(size_t)(s+1)*H];
                    a2 += wp[s+2]*ep[(size_t)(s+2)*H];
                    a3 += wp[s+3]*ep[(size_t)(s+3)*H];
                }
                g_x[b*X3H + H + h0] = (a0+a1+a2+a3)*inv;
            }
        }
        gridbar(bt);

        // ===== C: softmax + context (192) + resets (1)
        for (int task = W; task < 193; task += NW){
            if (task < 192){
                int b = task/24, c = task - b*24;
                int h0 = c*32 + lane;
                const float* sp = g_sc + b*SEQ;
                float mx = -1e30f;
                #pragma unroll
                for (int i = 0; i < 16; i++) mx = fmaxf(mx, sp[lane + 32*i]);
                #pragma unroll
                for (int o = 16; o; o >>= 1) mx = fmaxf(mx, __shfl_xor_sync(0xffffffffu, mx, o));
                float se = 0.f;
                #pragma unroll
                for (int i = 0; i < 16; i++) se += expf(sp[lane + 32*i] - mx);
                se = wred(se);
                float inv = 1.f/se;
                float acc = 0.f;
                const float* ep = enc + (size_t)b*SEQ*H + h0;
                for (int s0 = 0; s0 < SEQ; s0 += 32){
                    float w = expf(sp[s0 + lane] - mx)*inv;
                    #pragma unroll
                    for (int i = 0; i < 32; i++){
                        float wi = __shfl_sync(0xffffffffu, w, i);
                        acc += wi*ep[(size_t)(s0 + i)*H];
                    }
                }
                g_x[b*X3H + h0] = acc;
            } else {
                if (lane < 8){ g_amax[lane] = 0u; g_amax2[lane] = 0ull; }
            }
        }
        gridbar(bt);

        // ===== D: stage x into smem; GRU (1152 tasks, 2 rows x 8 batches)
        {
            const float4* gx4 = (const float4*)g_x;
            for (int m = tid; m < BATCH*X3H4; m += NTHR) xs4[m] = gx4[m];
            __syncthreads();
            for (int task = W; task < 1152; task += NW){
                int r0 = task*2;
                const float4* wiA = wih4 + (size_t)r0*X3H4;
                const float4* wiB = wiA + X3H4;
                const float4* whA = whh4 + (size_t)r0*H4;
                const float4* whB = whA + H4;
                float giA[8]={0,0,0,0,0,0,0,0}, giB[8]={0,0,0,0,0,0,0,0};
                float ghA[8]={0,0,0,0,0,0,0,0}, ghB[8]={0,0,0,0,0,0,0,0};
                for (int i = 0; i < 18; i++){
                    float4 wa = wiA[i*32 + lane], wb = wiB[i*32 + lane];
                    #pragma unroll
                    for (int b = 0; b < 8; b++){
                        float4 x = xs4[b*X3H4 + i*32 + lane];
                        giA[b] += wa.x*x.x + wa.y*x.y + wa.z*x.z + wa.w*x.w;
                        giB[b] += wb.x*x.x + wb.y*x.y + wb.z*x.z + wb.w*x.w;
                    }
                }
                #pragma unroll
                for (int i = 0; i < 6; i++){
                    float4 wa = whA[i*32 + lane], wb = whB[i*32 + lane];
                    #pragma unroll
                    for (int b = 0; b < 8; b++){
                        float4 h = hs4[b*H4 + i*32 + lane];
                        ghA[b] += wa.x*h.x + wa.y*h.y + wa.z*h.z + wa.w*h.w;
                        ghB[b] += wb.x*h.x + wb.y*h.y + wb.z*h.z + wb.w*h.w;
                    }
                }
                #pragma unroll
                for (int b = 0; b < 8; b++){
                    giA[b] = wred(giA[b]); giB[b] = wred(giB[b]);
                    ghA[b] = wred(ghA[b]); ghB[b] = wred(ghB[b]);
                }
                if (lane < 8){
                    #pragma unroll
                    for (int rr = 0; rr < 2; rr++){
                        int r = r0 + rr;
                        int g = r/H, j = r - g*H;
                        float gi = rr ? giB[0] : giA[0];
                        float gh = rr ? ghB[0] : ghA[0];
                        #pragma unroll
                        for (int b = 1; b < 8; b++){
                            if (lane == b){ gi = rr ? giB[b] : giA[b]; gh = rr ? ghB[b] : ghA[b]; }
                        }
                        float bi = bih[r], bh_ = bhh[r];
                        if (g < 2) g_gRZ[g][lane][j] = gi + gh + bi + bh_;
                        else { g_gNi[lane][j] = gi + bi; g_gNh[lane][j] = gh + bh_; }
                    }
                }
            }
        }
        gridbar(bt);

        // ===== E: combine h locally; th2 (1536) + gen [0,GEN_E)
        {
            if (tid < 8) bmax[tid] = 0u;
            for (int m = tid; m < BATCH*H4; m += NTHR){
                int b = m/H4, c = m - b*H4;
                float4 r0 = ((const float4*)g_gRZ[0][b])[c];
                float4 r1 = ((const float4*)g_gRZ[1][b])[c];
                float4 ni = ((const float4*)g_gNi[b])[c];
                float4 nh = ((const float4*)g_gNh[b])[c];
                float4 ho = hs4[m];
                float4 hv;
                hv.x = gruc(r0.x, r1.x, ni.x, nh.x, ho.x);
                hv.y = gruc(r0.y, r1.y, ni.y, nh.y, ho.y);
                hv.z = gruc(r0.z, r1.z, ni.z, nh.z, ho.z);
                hv.w = gruc(r0.w, r1.w, ni.w, nh.w, ho.w);
                hs4[m] = hv;
            }
            __syncthreads();
        }
        for (int task = W; task < 1536 + GEN_E; task += NW){
            if (task < 1536){
                int bh = task & 1, j = task >> 1;
                int b0 = bh*4;
                const float4* r4 = cw4 + (size_t)j*H4;
                float a0=0,a1=0,a2=0,a3=0;
                #pragma unroll
                for (int i = 0; i < 6; i++){
                    float4 w = r4[i*32 + lane];
                    float4 h0 = hs4[(b0+0)*H4 + i*32 + lane];
                    float4 h1 = hs4[(b0+1)*H4 + i*32 + lane];
                    float4 h2 = hs4[(b0+2)*H4 + i*32 + lane];
                    float4 h3 = hs4[(b0+3)*H4 + i*32 + lane];
                    a0 += w.x*h0.x + w.y*h0.y + w.z*h0.z + w.w*h0.w;
                    a1 += w.x*h1.x + w.y*h1.y + w.z*h1.z + w.w*h1.w;
                    a2 += w.x*h2.x + w.y*h2.y + w.z*h2.z + w.w*h2.w;
                    a3 += w.x*h3.x + w.y*h3.y + w.z*h3.z + w.w*h3.w;
                }
                a0 = wred(a0); a1 = wred(a1); a2 = wred(a2); a3 = wred(a3);
                if (!lane){
                    float bb = cb[j];
                    g_th2[(b0+0)*H + j] = a0 + bb;
                    g_th2[(b0+1)*H + j] = a1 + bb;
                    g_th2[(b0+2)*H + j] = a2 + bb;
                    g_th2[(b0+3)*H + j] = a3 + bb;
                }
            } else {
                int blk = task - 1536;
                int v0 = blk*4;
                const float4* w0 = ow4 + (size_t)v0*H4;
                const float4* w1 = ow4 + (size_t)min(v0+1, VOC-1)*H4;
                const float4* w2 = ow4 + (size_t)min(v0+2, VOC-1)*H4;
                const float4* w3 = ow4 + (size_t)min(v0+3, VOC-1)*H4;
                float acc0[8]={0,0,0,0,0,0,0,0}, acc1[8]={0,0,0,0,0,0,0,0};
                float acc2[8]={0,0,0,0,0,0,0,0}, acc3[8]={0,0,0,0,0,0,0,0};
                #pragma unroll
                for (int i = 0; i < 6; i++){
                    float4 a = w0[i*32+lane], b_ = w1[i*32+lane];
                    float4 c = w2[i*32+lane], d = w3[i*32+lane];
                    #pragma unroll
                    for (int b2 = 0; b2 < 8; b2++){
                        float4 h = hs4[b2*H4 + i*32 + lane];
                        acc0[b2] += a.x*h.x + a.y*h.y + a.z*h.z + a.w*h.w;
                        acc1[b2] += b_.x*h.x + b_.y*h.y + b_.z*h.z + b_.w*h.w;
                        acc2[b2] += c.x*h.x + c.y*h.y + c.z*h.z + c.w*h.w;
                        acc3[b2] += d.x*h.x + d.y*h.y + d.z*h.z + d.w*h.w;
                    }
                }
                #pragma unroll
                for (int b2 = 0; b2 < 8; b2++){
                    acc0[b2] = wred(acc0[b2]); acc1[b2] = wred(acc1[b2]);
                    acc2[b2] = wred(acc2[b2]); acc3[b2] = wred(acc3[b2]);
                }
                if (lane < 8){
                    #pragma unroll
                    for (int vv = 0; vv < 4; vv++){
                        int v = v0 + vv;
                        if (v < VOC){
                            float g = (vv==0) ? acc0[0] : (vv==1) ? acc1[0] : (vv==2) ? acc2[0] : acc3[0];
                            #pragma unroll
                            for (int b2 = 1; b2 < 8; b2++)
                                if (lane == b2) g = (vv==0) ? acc0[b2] : (vv==1) ? acc1[b2] : (vv==2) ? acc2[b2] : acc3[b2];
                            g += ob[v];
                            if (v == 0) g = NEGV;
                            g_gen[(size_t)v*8 + lane] = g;
                            atomicMax(&bmax[lane], okey(g));
                        }
                    }
                }
            }
        }
        gridbar(bt);

        // ===== F: css (4096) + gen [GEN_E, GEN_F)
        for (int task = W; task < 4096 + (GEN_F - GEN_E); task += NW){
            if (task < 4096){
                int b = task >> 9, s = task & 511;
                const float4* e4 = (const float4*)(enc + ((size_t)b*SEQ + s)*H);
                const float4* t4 = (const float4*)(g_th2 + b*H);
                float a = 0.f;
                #pragma unroll
                for (int i = 0; i < 6; i++){
                    float4 x = e4[i*32 + lane], y = t4[i*32 + lane];
                    a += x.x*y.x + x.y*y.y + x.z*y.z + x.w*y.w;
                }
                a = wred(a);
                if (!lane) g_css[b*SEQ + s] = a;
            } else {
                int blk = GEN_E + (task - 4096);
                int v0 = blk*4;
                const float4* w0 = ow4 + (size_t)v0*H4;
                const float4* w1 = ow4 + (size_t)(v0+1)*H4;
                const float4* w2 = ow4 + (size_t)(v0+2)*H4;
                const float4* w3 = ow4 + (size_t)(v0+3)*H4;
                float acc0[8]={0,0,0,0,0,0,0,0}, acc1[8]={0,0,0,0,0,0,0,0};
                float acc2[8]={0,0,0,0,0,0,0,0}, acc3[8]={0,0,0,0,0,0,0,0};
                #pragma unroll
                for (int i = 0; i < 6; i++){
                    float4 a = w0[i*32+lane], b_ = w1[i*32+lane];
                    float4 c = w2[i*32+lane], d = w3[i*32+lane];
                    #pragma unroll
                    for (int b2 = 0; b2 < 8; b2++){
                        float4 h = hs4[b2*H4 + i*32 + lane];
                        acc0[b2] += a.x*h.x + a.y*h.y + a.z*h.z + a.w*h.w;
                        acc1[b2] += b_.x*h.x + b_.y*h.y + b_.z*h.z + b_.w*h.w;
                        acc2[b2] += c.x*h.x + c.y*h.y + c.z*h.z + c.w*h.w;
                        acc3[b2] += d.x*h.x + d.y*h.y + d.z*h.z + d.w*h.w;
                    }
                }
                #pragma unroll
                for (int b2 = 0; b2 < 8; b2++){
                    acc0[b2] = wred(acc0[b2]); acc1[b2] = wred(acc1[b2]);
                    acc2[b2] = wred(acc2[b2]); acc3[b2] = wred(acc3[b2]);
                }
                if (lane < 8){
                    #pragma unroll
                    for (int vv = 0; vv < 4; vv++){
                        int v = v0 + vv;
                        float g = (vv==0) ? acc0[0] : (vv==1) ? acc1[0] : (vv==2) ? acc2[0] : acc3[0];
                        #pragma unroll
                        for (int b2 = 1; b2 < 8; b2++)
                            if (lane == b2) g = (vv==0) ? acc0[b2] : (vv==1) ? acc1[b2] : (vv==2) ? acc2[b2] : acc3[b2];
                        g += ob[v];
                        g_gen[(size_t)v*8 + lane] = g;
                        atomicMax(&bmax[lane], okey(g));
                    }
                }
            }
        }
        gridbar(bt);

        // ===== G: copy-chain (128) + gen [GEN_F, GBLK); flush bmax
        for (int task = W; task < 128 + (GBLK - GEN_F); task += NW){
            if (task < 128){
                int b = task >> 4, ch = task & 15;
                int s = ch*32 + lane;
                if (g_fo[b*SEQ + s]){
                    int tok = inputs[b*SEQ + s];
                    const int* ip = inputs + b*SEQ;
                    const float* cp = g_css + b*SEQ;
                    float sum = 0.f;
                    for (int s2 = 0; s2 < SEQ; s2++)
                        if (ip[s2] == tok) sum += cp[s2];
                    g_copyval[b*VOC + tok] = sum;
                    atomicMax(&bmax[b], okey(sum));
                }
            } else {
                int blk = GEN_F + (task - 128);
                int v0 = blk*4;
                const float4* w0 = ow4 + (size_t)v0*H4;
                const float4* w1 = ow4 + (size_t)min(v0+1, VOC-1)*H4;
                const float4* w2 = ow4 + (size_t)min(v0+2, VOC-1)*H4;
                const float4* w3 = ow4 + (size_t)min(v0+3, VOC-1)*H4;
                float acc0[8]={0,0,0,0,0,0,0,0}, acc1[8]={0,0,0,0,0,0,0,0};
                float acc2[8]={0,0,0,0,0,0,0,0}, acc3[8]={0,0,0,0,0,0,0,0};
                #pragma unroll
                for (int i = 0; i < 6; i++){
                    float4 a = w0[i*32+lane], b_ = w1[i*32+lane];
                    float4 c = w2[i*32+lane], d = w3[i*32+lane];
                    #pragma unroll
                    for (int b2 = 0; b2 < 8; b2++){
                        float4 h = hs4[b2*H4 + i*32 + lane];
                        acc0[b2] += a.x*h.x + a.y*h.y + a.z*h.z + a.w*h.w;
                        acc1[b2] += b_.x*h.x + b_.y*h.y + b_.z*h.z + b_.w*h.w;
                        acc2[b2] += c.x*h.x + c.y*h.y + c.z*h.z + c.w*h.w;
                        acc3[b2] += d.x*h.x + d.y*h.y + d.z*h.z + d.w*h.w;
                    }
                }
                #pragma unroll
                for (int b2 = 0; b2 < 8; b2++){
                    acc0[b2] = wred(acc0[b2]); acc1[b2] = wred(acc1[b2]);
                    acc2[b2] = wred(acc2[b2]); acc3[b2] = wred(acc3[b2]);
                }
                if (lane < 8){
                    #pragma unroll
                    for (int vv = 0; vv < 4; vv++){
                        int v = v0 + vv;
                        if (v < VOC){
                            float g = (vv==0) ? acc0[0] : (vv==1) ? acc1[0] : (vv==2) ? acc2[0] : acc3[0];
                            #pragma unroll
                            for (int b2 = 1; b2 < 8; b2++)
                                if (lane == b2) g = (vv==0) ? acc0[b2] : (vv==1) ? acc1[b2] : (vv==2) ? acc2[b2] : acc3[b2];
                            g += ob[v];
                            g_gen[(size_t)v*8 + lane] = g;
                            atomicMax(&bmax[lane], okey(g));
                        }
                    }
                }
            }
        }
        __syncthreads();
        if (tid < 8) atomicMax(&g_amax[tid], bmax[tid]);
        gridbar(bt);

        // ===== H: deterministic Z partials + copy-Z
        {
            float m8[8];
            #pragma unroll
            for (int b = 0; b < 8; b++) m8[b] = dekey(g_amax[b]);
            int v0 = cta*ZCH;
            int cnt = min(ZCH, VOC - v0);
            float e[8] = {0,0,0,0,0,0,0,0};
            if (tid < cnt){
                int v = v0 + tid;
                float4 a = ((const float4*)g_gen)[(size_t)v*2];
                float4 c = ((const float4*)g_gen)[(size_t)v*2 + 1];
                e[0] = expf(a.x - m8[0]); e[1] = expf(a.y - m8[1]);
                e[2] = expf(a.z - m8[2]); e[3] = expf(a.w - m8[3]);
                e[4] = expf(c.x - m8[4]); e[5] = expf(c.y - m8[5]);
                e[6] = expf(c.z - m8[6]); e[7] = expf(c.w - m8[7]);
            }
            #pragma unroll
            for (int o = 16; o; o >>= 1){
                #pragma unroll
                for (int b = 0; b < 8; b++) e[b] += __shfl_xor_sync(0xffffffffu, e[b], o);
            }
            if (!lane){
                #pragma unroll
                for (int b = 0; b < 8; b++) zred[wid][b] = e[b];
            }
            __syncthreads();
            if (wid < 8){
                float v = (lane < NWARP) ? zred[lane][wid] : 0.f;
                v = wred(v);
                if (!lane) g_Zp[cta][wid] = v;
            }
            if (cta == NCTA - 1 && wid >= 8){
                int b = wid - 8;
                float e2 = 0.f;
                for (int s = lane; s < SEQ; s += 32)
                    if (g_fo[b*SEQ + s])
                        e2 += expf(g_copyval[b*VOC + inputs[b*SEQ + s]] - m8[b]);
                e2 = wred(e2);
                if (!lane) g_Zp[NCTA][b] = e2;
            }
        }
        gridbar(bt);

        // ===== I: log-prob row + argmax
        {
            if (tid < 8){ msh[tid] = dekey(g_amax[tid]); bkey[tid] = 0ull; }
            if (wid < 8){
                float z = 0.f;
                for (int i = lane; i <= NCTA; i += 32) z += g_Zp[i][wid];
                z = wred(z);
                if (!lane) zinv[wid] = 1.f/z;
            }
            __syncthreads();
            int v0 = cta*ZCH;
            int cnt = min(ZCH, VOC - v0);
            if (tid < cnt){
                int v = v0 + tid;
                float4 a = ((const float4*)g_gen)[(size_t)v*2];
                float4 c = ((const float4*)g_gen)[(size_t)v*2 + 1];
                float gv[8] = {a.x, a.y, a.z, a.w, c.x, c.y, c.z, c.w};
                unsigned int vk = (unsigned int)(0x7FFFFFFF - v);
                #pragma unroll
                for (int b = 0; b < 8; b++){
                    float p = expf(gv[b] - msh[b])*zinv[b];
                    if (g_present[b*VOC + v])
                        p += expf(g_copyval[b*VOC + v] - msh[b])*zinv[b];
                    float lp = logf(p + 1e-10f);
                    out[((size_t)b*TMAXX + t)*EXT + v] = lp;
                    unsigned long long key = (((unsigned long long)okey(lp)) << 32) | vk;
                    atomicMax(&bkey[b], key);
                }
            }
            __syncthreads();
            if (tid < 8) atomicMax(&g_amax2[tid], bkey[tid]);
        }
        gridbar(bt);
    }

    if (cta == 0 && tid < 8 && has_tail){
        unsigned long long key = g_amax2[tid];
        int samp = 0x7FFFFFFF - (int)(unsigned int)(key & 0xFFFFFFFFull);
        out[D1 + tid*TMAXX + (TMAXX - 1)] = (float)samp;
    }
}

// ---------------- host ----------------
extern "C" void kernel_launch(void* const* d_in, const int* in_sizes, int n_in,
                              void* d_out, int out_size){
    const float* enc    = (const float*)d_in[0];
    const int*   inputs = (const int*)  d_in[1];
    const int*   cls    = (const int*)  d_in[2];
    /* d_in[3] sep_to unused */
    const float* emb    = (const float*)d_in[4];
    const float* aw     = (const float*)d_in[5];
    const float* ab     = (const float*)d_in[6];
    const float* cw     = (const float*)d_in[7];
    const float* cb     = (const float*)d_in[8];
    const float* wih    = (const float*)d_in[9];
    const float* whh    = (const float*)d_in[10];
    const float* bih    = (const float*)d_in[11];
    const float* bhh    = (const float*)d_in[12];
    const float* ow     = (const float*)d_in[13];
    const float* ob     = (const float*)d_in[14];
    float* out = (float*)d_out;
    int has_tail = (out_size >= D1 + BATCH*TMAXX) ? 1 : 0;

    const int smemsz = (BATCH*X3H + BATCH*H)*sizeof(float);   // 96 KB
    cudaFuncSetAttribute(k_loop, cudaFuncAttributeMaxDynamicSharedMemorySize, smemsz);

    k_init<<<512, 256>>>(cls, emb, out, has_tail);
    k_prep<<<BATCH, SEQ>>>(inputs);
    k_loop<<<NCTA, NTHR, smemsz>>>(enc, inputs, emb,
                                   (const float4*)aw, ab,
                                   (const float4*)cw, cb,
                                   (const float4*)wih, (const float4*)whh,
                                   bih, bhh,
                                   (const float4*)ow, ob,
                                   out, has_tail);
}